// round 3
// baseline (speedup 1.0000x reference)
#include <cuda_runtime.h>
#include <cstdint>
#include <cstddef>

// ---------------------------------------------------------------------------
// MPNN-GNN: V=20000 nodes, E=100000 edges, H=64, 9 message-passing steps.
// Plan:
//   h    = (relu(node @ Wp1^T + bp1)) @ Wp2^T + bp2                  (V,64)
//   R    = relu(edge  @ We1^T + be1)                                  (E,128)
//   We   = R @ We2^T + be2           (materialized once, 1.6 GB)      (E,4096)
//   9x: msg[e,o] = sum_i h[src_e,i]*We[e,i*64+o]; agg = scatter_add(dst)
//       x = relu(agg + b_conv); GI = x@Wih^T+bih; GH = h@Whh^T+bhh
//       r=sig(GI_r+GH_r); z=sig(GI_z+GH_z); n=tanh(GI_n + r*GH_n)
//       h = (1-z)*n + z*h
//   out  = (relu(h @ Wd1^T + bd1)) @ Wd2^T + bd2
// ---------------------------------------------------------------------------

#define V_MAX 20000
#define E_MAX 100000

// Scratch (device-global; allocation-free per harness rules)
__device__ float g_We[(size_t)E_MAX * 4096];   // 1.64 GB
__device__ float g_R [(size_t)E_MAX * 128];    // 51 MB
__device__ float g_t [(size_t)V_MAX * 64];
__device__ float g_h [(size_t)V_MAX * 64];
__device__ float g_agg[(size_t)V_MAX * 64];
__device__ float g_x [(size_t)V_MAX * 64];
__device__ float g_gi[(size_t)V_MAX * 192];
__device__ float g_gh[(size_t)V_MAX * 192];
__device__ float g_d1[(size_t)V_MAX * 64];

// ---------------------------------------------------------------------------
// Generic tiled SGEMM computing C[M,N] = A[M,K] * B[N,K]^T + bias[N] (+relu)
// A, B both row-major with K contiguous (exactly the "x @ W^T" pattern).
// Requires K % BK == 0 (all our K are 64 or 128), N % 4 == 0, 16B-aligned ptrs.
// grid.x tiles N (so a concurrent wave reuses A tiles via L2), grid.y tiles M.
// ---------------------------------------------------------------------------
template <int BM, int BN, int BK, int TM, int TN, bool RELU>
__global__ __launch_bounds__((BM / TM) * (BN / TN))
void sgemm_nt(const float* __restrict__ A, const float* __restrict__ B,
              const float* __restrict__ bias, float* __restrict__ C,
              int M, int N, int K)
{
    constexpr int THREADS = (BM / TM) * (BN / TN);
    __shared__ float As[BK][BM];
    __shared__ float Bs[BK][BN];

    const int tid = threadIdx.x;
    const int tx  = tid % (BN / TN);
    const int ty  = tid / (BN / TN);
    const int n0  = blockIdx.x * BN;
    const int m0  = blockIdx.y * BM;

    constexpr int A_PER_T = (BM * BK / 4) / THREADS;  // float4 loads per thread
    constexpr int B_PER_T = (BN * BK / 4) / THREADS;
    static_assert(A_PER_T >= 1 && B_PER_T >= 1, "tile/thread mismatch");

    float acc[TM][TN];
#pragma unroll
    for (int i = 0; i < TM; i++)
#pragma unroll
        for (int j = 0; j < TN; j++) acc[i][j] = 0.f;

    for (int k0 = 0; k0 < K; k0 += BK) {
        // --- load A tile (transposed into shared) ---
#pragma unroll
        for (int v = 0; v < A_PER_T; v++) {
            int idx = (tid + v * THREADS) * 4;      // element idx in [BM][BK]
            int r = idx / BK, c = idx % BK;
            float4 val = make_float4(0.f, 0.f, 0.f, 0.f);
            if (m0 + r < M)
                val = *reinterpret_cast<const float4*>(A + (size_t)(m0 + r) * K + k0 + c);
            As[c + 0][r] = val.x; As[c + 1][r] = val.y;
            As[c + 2][r] = val.z; As[c + 3][r] = val.w;
        }
        // --- load B tile (transposed into shared) ---
#pragma unroll
        for (int v = 0; v < B_PER_T; v++) {
            int idx = (tid + v * THREADS) * 4;
            int r = idx / BK, c = idx % BK;
            float4 val = make_float4(0.f, 0.f, 0.f, 0.f);
            if (n0 + r < N)
                val = *reinterpret_cast<const float4*>(B + (size_t)(n0 + r) * K + k0 + c);
            Bs[c + 0][r] = val.x; Bs[c + 1][r] = val.y;
            Bs[c + 2][r] = val.z; Bs[c + 3][r] = val.w;
        }
        __syncthreads();

#pragma unroll
        for (int kk = 0; kk < BK; kk++) {
            float a[TM], b[TN];
#pragma unroll
            for (int i = 0; i < TM; i += 4)
                *reinterpret_cast<float4*>(&a[i]) =
                    *reinterpret_cast<const float4*>(&As[kk][ty * TM + i]);
#pragma unroll
            for (int j = 0; j < TN; j += 4)
                *reinterpret_cast<float4*>(&b[j]) =
                    *reinterpret_cast<const float4*>(&Bs[kk][tx * TN + j]);
#pragma unroll
            for (int i = 0; i < TM; i++)
#pragma unroll
                for (int j = 0; j < TN; j++)
                    acc[i][j] += a[i] * b[j];
        }
        __syncthreads();
    }

    // --- epilogue: bias (+relu), vectorized stores (N % 4 == 0 always) ---
#pragma unroll
    for (int i = 0; i < TM; i++) {
        int row = m0 + ty * TM + i;
        if (row >= M) continue;
#pragma unroll
        for (int j = 0; j < TN; j += 4) {
            int col = n0 + tx * TN + j;
            if (col >= N) continue;
            float4 bv = *reinterpret_cast<const float4*>(&bias[col]);
            float4 o;
            o.x = acc[i][j + 0] + bv.x;
            o.y = acc[i][j + 1] + bv.y;
            o.z = acc[i][j + 2] + bv.z;
            o.w = acc[i][j + 3] + bv.w;
            if (RELU) {
                o.x = fmaxf(o.x, 0.f); o.y = fmaxf(o.y, 0.f);
                o.z = fmaxf(o.z, 0.f); o.w = fmaxf(o.w, 0.f);
            }
            *reinterpret_cast<float4*>(&C[(size_t)row * N + col]) = o;
        }
    }
}

// ---------------------------------------------------------------------------
// NNConv message + scatter: msg[e,o] = sum_i h[src_e,i] * We[e, i*64+o];
// atomicAdd into agg[dst_e*64+o]. 64 threads per edge (coalesced 256B per i),
// 4 edges per 256-thread block. HBM-bound on We reads.
// ---------------------------------------------------------------------------
__global__ __launch_bounds__(256)
void msg_scatter(const float* __restrict__ h, const float* __restrict__ We,
                 const int* __restrict__ src, const int* __restrict__ dst,
                 float* __restrict__ agg, int E)
{
    const int eg = threadIdx.x >> 6;   // edge slot in block (0..3)
    const int o  = threadIdx.x & 63;
    const int e  = blockIdx.x * 4 + eg;
    __shared__ float hs[4][64];

    const bool valid = e < E;
    int s = 0, d = 0;
    if (valid) { s = src[e]; d = dst[e]; }
    hs[eg][o] = valid ? h[s * 64 + o] : 0.f;
    __syncthreads();

    if (valid) {
        const float* w = We + (size_t)e * 4096 + o;
        float acc = 0.f;
#pragma unroll
        for (int i = 0; i < 64; i++)
            acc += hs[eg][i] * w[(size_t)i * 64];
        atomicAdd(&agg[d * 64 + o], acc);
    }
}

// x = relu(agg + b_conv); agg reset to 0 for next step's scatter
__global__ void xrelu_kernel(float* __restrict__ agg, const float* __restrict__ b_conv,
                             float* __restrict__ x, int total)
{
    int i = blockIdx.x * blockDim.x + threadIdx.x;
    if (i < total) {
        float v = agg[i] + b_conv[i & 63];
        x[i]   = fmaxf(v, 0.f);
        agg[i] = 0.f;
    }
}

// GRU gate nonlinearity + state update (in place on h)
__global__ void gru_gates(const float* __restrict__ gi, const float* __restrict__ gh,
                          float* __restrict__ h, int total)
{
    int i = blockIdx.x * blockDim.x + threadIdx.x;
    if (i < total) {
        int v = i >> 6, j = i & 63;
        const float* giv = gi + (size_t)v * 192;
        const float* ghv = gh + (size_t)v * 192;
        float r = 1.f / (1.f + expf(-(giv[j]       + ghv[j])));
        float z = 1.f / (1.f + expf(-(giv[64 + j]  + ghv[64 + j])));
        float n = tanhf(giv[128 + j] + r * ghv[128 + j]);
        h[i] = (1.f - z) * n + z * h[i];
    }
}

// ---------------------------------------------------------------------------
// Host-side launch helpers
// ---------------------------------------------------------------------------
template <bool RELU>
static void sgemm_big(const float* A, const float* B, const float* bias, float* C,
                      int M, int N, int K)
{
    dim3 grid((N + 127) / 128, (M + 127) / 128);
    sgemm_nt<128, 128, 16, 8, 8, RELU><<<grid, 256>>>(A, B, bias, C, M, N, K);
}

template <bool RELU>
static void sgemm_sm(const float* A, const float* B, const float* bias, float* C,
                     int M, int N, int K)
{
    dim3 grid((N + 63) / 64, (M + 63) / 64);
    sgemm_nt<64, 64, 16, 4, 4, RELU><<<grid, 256>>>(A, B, bias, C, M, N, K);
}

extern "C" void kernel_launch(void* const* d_in, const int* in_sizes, int n_in,
                              void* d_out, int out_size)
{
    const float* node_feats = (const float*)d_in[0];
    const float* edge_feats = (const float*)d_in[1];
    const int*   src        = (const int*)  d_in[2];
    const int*   dst        = (const int*)  d_in[3];
    const float* w_p1 = (const float*)d_in[4];
    const float* b_p1 = (const float*)d_in[5];
    const float* w_p2 = (const float*)d_in[6];
    const float* b_p2 = (const float*)d_in[7];
    const float* w_e1 = (const float*)d_in[8];
    const float* b_e1 = (const float*)d_in[9];
    const float* w_e2 = (const float*)d_in[10];
    const float* b_e2 = (const float*)d_in[11];
    const float* b_conv = (const float*)d_in[12];
    const float* w_ih = (const float*)d_in[13];
    const float* w_hh = (const float*)d_in[14];
    const float* b_ih = (const float*)d_in[15];
    const float* b_hh = (const float*)d_in[16];
    const float* w_d1 = (const float*)d_in[17];
    const float* b_d1 = (const float*)d_in[18];
    const float* w_d2 = (const float*)d_in[19];
    const float* b_d2 = (const float*)d_in[20];

    const int V = in_sizes[0] / 128;   // 20000
    const int E = in_sizes[2];         // 100000

    float *We, *R, *t, *h, *agg, *x, *gi, *gh, *d1;
    cudaGetSymbolAddress((void**)&We,  g_We);
    cudaGetSymbolAddress((void**)&R,   g_R);
    cudaGetSymbolAddress((void**)&t,   g_t);
    cudaGetSymbolAddress((void**)&h,   g_h);
    cudaGetSymbolAddress((void**)&agg, g_agg);
    cudaGetSymbolAddress((void**)&x,   g_x);
    cudaGetSymbolAddress((void**)&gi,  g_gi);
    cudaGetSymbolAddress((void**)&gh,  g_gh);
    cudaGetSymbolAddress((void**)&d1,  g_d1);

    const int nv = V * 64;
    const int ew = (nv + 255) / 256;

    // agg must be zero before the first scatter (xrelu re-zeroes it each step)
    cudaMemsetAsync(agg, 0, (size_t)nv * sizeof(float), 0);

    // node projection: h = (relu(node @ Wp1^T + bp1)) @ Wp2^T + bp2
    sgemm_sm<true >(node_feats, w_p1, b_p1, t, V, 64, 128);
    sgemm_sm<false>(t,          w_p2, b_p2, h, V, 64, 64);

    // edge network: R = relu(edge @ We1^T + be1); We = R @ We2^T + be2
    sgemm_big<true >(edge_feats, w_e1, b_e1, R,  E, 128,  128);
    sgemm_big<false>(R,          w_e2, b_e2, We, E, 4096, 128);

    // 9 message-passing steps
    for (int step = 0; step < 9; step++) {
        msg_scatter<<<(E + 3) / 4, 256>>>(h, We, src, dst, agg, E);
        xrelu_kernel<<<ew, 256>>>(agg, b_conv, x, nv);
        sgemm_sm<false>(x, w_ih, b_ih, gi, V, 192, 64);
        sgemm_sm<false>(h, w_hh, b_hh, gh, V, 192, 64);
        gru_gates<<<ew, 256>>>(gi, gh, h, nv);
    }

    // decoder: out = (relu(h @ Wd1^T + bd1)) @ Wd2^T + bd2
    sgemm_sm<true >(h,  w_d1, b_d1, d1,            V, 64, 64);
    sgemm_sm<false>(d1, w_d2, b_d2, (float*)d_out, V, 64, 64);
}

// round 5
// speedup vs baseline: 1.0818x; 1.0818x over previous
#include <cuda_runtime.h>
#include <cstdint>
#include <cstddef>

// ---------------------------------------------------------------------------
// MPNN-GNN: V=20000, E=100000, H=64, 9 steps.
//   A2 (V,128) holds [x | h] concatenated per node.
//   We (E,4096) materialized once; read 9x by the scatter (DRAM floor).
//   Fused GRU weight W' (256,128): one GEMM/step gives [r_sum, z_sum, i_n, h_n].
// ---------------------------------------------------------------------------

#define V_MAX 20000
#define E_MAX 100000

__device__ float g_We [(size_t)E_MAX * 4096];   // 1.64 GB
__device__ float g_R  [(size_t)E_MAX * 128];    // 51 MB
__device__ float g_A2 [(size_t)V_MAX * 128];    // [x | h]
__device__ float g_G  [(size_t)V_MAX * 256];    // fused GRU pre-activations
__device__ float g_t  [(size_t)V_MAX * 64];
__device__ float g_agg[(size_t)V_MAX * 64];
__device__ float g_d1 [(size_t)V_MAX * 64];
__device__ float g_Wg [256 * 128];
__device__ float g_bg [256];

// ---------------------------------------------------------------------------
// Double-buffered tiled SGEMM: C[M,N] = A[M,K] * B[N,K]^T + bias[N] (+relu)
// A row-major with leading dim lda (K contiguous), B dense (N,K), C ldc.
// K % BK == 0 required (all K are 64 or 128). 2-stage smem pipeline:
// prefetch next K-slab into regs while computing current slab, one sync/iter.
// ---------------------------------------------------------------------------
template <int BM, int BN, int BK, int TM, int TN, bool RELU>
__global__ __launch_bounds__((BM / TM) * (BN / TN), 2)
void sgemm_db(const float* __restrict__ A, int lda,
              const float* __restrict__ B,
              const float* __restrict__ bias,
              float* __restrict__ C, int ldc,
              int M, int N, int K)
{
    constexpr int THREADS = (BM / TM) * (BN / TN);
    constexpr int APT = (BM * BK / 4) / THREADS;   // float4 A loads / thread
    constexpr int BPT = (BN * BK / 4) / THREADS;
    static_assert(APT >= 1 && BPT >= 1, "tile config");

    __shared__ float As[2][BK][BM];
    __shared__ float Bs[2][BK][BN];

    const int tid = threadIdx.x;
    const int tx  = tid % (BN / TN);
    const int ty  = tid / (BN / TN);
    const int n0  = blockIdx.x * BN;
    const int m0  = blockIdx.y * BM;

    const float4 z4 = make_float4(0.f, 0.f, 0.f, 0.f);

    const float* aptr[APT]; int ac[APT], ar[APT]; bool aok[APT];
#pragma unroll
    for (int v = 0; v < APT; v++) {
        int idx = (tid + v * THREADS) * 4;
        ar[v] = idx / BK; ac[v] = idx % BK;
        aok[v] = (m0 + ar[v]) < M;
        aptr[v] = A + (size_t)(m0 + ar[v]) * lda + ac[v];
    }
    const float* bptr[BPT]; int bc[BPT], br[BPT]; bool bok[BPT];
#pragma unroll
    for (int v = 0; v < BPT; v++) {
        int idx = (tid + v * THREADS) * 4;
        br[v] = idx / BK; bc[v] = idx % BK;
        bok[v] = (n0 + br[v]) < N;
        bptr[v] = B + (size_t)(n0 + br[v]) * K + bc[v];
    }

    float4 pa[APT], pb[BPT];
    // prologue: fetch slab 0, stage into buffer 0
#pragma unroll
    for (int v = 0; v < APT; v++) pa[v] = aok[v] ? *(const float4*)(aptr[v]) : z4;
#pragma unroll
    for (int v = 0; v < BPT; v++) pb[v] = bok[v] ? *(const float4*)(bptr[v]) : z4;
#pragma unroll
    for (int v = 0; v < APT; v++) {
        As[0][ac[v] + 0][ar[v]] = pa[v].x; As[0][ac[v] + 1][ar[v]] = pa[v].y;
        As[0][ac[v] + 2][ar[v]] = pa[v].z; As[0][ac[v] + 3][ar[v]] = pa[v].w;
    }
#pragma unroll
    for (int v = 0; v < BPT; v++) {
        Bs[0][bc[v] + 0][br[v]] = pb[v].x; Bs[0][bc[v] + 1][br[v]] = pb[v].y;
        Bs[0][bc[v] + 2][br[v]] = pb[v].z; Bs[0][bc[v] + 3][br[v]] = pb[v].w;
    }
    __syncthreads();

    float acc[TM][TN];
#pragma unroll
    for (int i = 0; i < TM; i++)
#pragma unroll
        for (int j = 0; j < TN; j++) acc[i][j] = 0.f;

    int buf = 0;
    for (int k0 = 0; k0 < K; k0 += BK) {
        const bool more = (k0 + BK) < K;
        if (more) {
#pragma unroll
            for (int v = 0; v < APT; v++)
                pa[v] = aok[v] ? *(const float4*)(aptr[v] + k0 + BK) : z4;
#pragma unroll
            for (int v = 0; v < BPT; v++)
                pb[v] = bok[v] ? *(const float4*)(bptr[v] + k0 + BK) : z4;
        }
#pragma unroll
        for (int kk = 0; kk < BK; kk++) {
            float a[TM], b[TN];
#pragma unroll
            for (int i = 0; i < TM; i += 4)
                *reinterpret_cast<float4*>(&a[i]) =
                    *reinterpret_cast<const float4*>(&As[buf][kk][ty * TM + i]);
#pragma unroll
            for (int j = 0; j < TN; j += 4)
                *reinterpret_cast<float4*>(&b[j]) =
                    *reinterpret_cast<const float4*>(&Bs[buf][kk][tx * TN + j]);
#pragma unroll
            for (int i = 0; i < TM; i++)
#pragma unroll
                for (int j = 0; j < TN; j++)
                    acc[i][j] += a[i] * b[j];
        }
        if (more) {
#pragma unroll
            for (int v = 0; v < APT; v++) {
                As[buf ^ 1][ac[v] + 0][ar[v]] = pa[v].x; As[buf ^ 1][ac[v] + 1][ar[v]] = pa[v].y;
                As[buf ^ 1][ac[v] + 2][ar[v]] = pa[v].z; As[buf ^ 1][ac[v] + 3][ar[v]] = pa[v].w;
            }
#pragma unroll
            for (int v = 0; v < BPT; v++) {
                Bs[buf ^ 1][bc[v] + 0][br[v]] = pb[v].x; Bs[buf ^ 1][bc[v] + 1][br[v]] = pb[v].y;
                Bs[buf ^ 1][bc[v] + 2][br[v]] = pb[v].z; Bs[buf ^ 1][bc[v] + 3][br[v]] = pb[v].w;
            }
        }
        __syncthreads();
        buf ^= 1;
    }

    // epilogue: bias (+relu), vectorized stores (all N % 4 == 0)
#pragma unroll
    for (int i = 0; i < TM; i++) {
        int row = m0 + ty * TM + i;
        if (row >= M) continue;
#pragma unroll
        for (int j = 0; j < TN; j += 4) {
            int col = n0 + tx * TN + j;
            if (col >= N) continue;
            float4 bv = *reinterpret_cast<const float4*>(&bias[col]);
            float4 o;
            o.x = acc[i][j + 0] + bv.x; o.y = acc[i][j + 1] + bv.y;
            o.z = acc[i][j + 2] + bv.z; o.w = acc[i][j + 3] + bv.w;
            if (RELU) {
                o.x = fmaxf(o.x, 0.f); o.y = fmaxf(o.y, 0.f);
                o.z = fmaxf(o.z, 0.f); o.w = fmaxf(o.w, 0.f);
            }
            *reinterpret_cast<float4*>(&C[(size_t)row * ldc + col]) = o;
        }
    }
}

// ---------------------------------------------------------------------------
// NNConv message + scatter. One warp per edge; 32 lanes x float2 -> 64 outs.
// h lives in A2[:,64:128] (stride 128). We streamed with __ldcs (evict-first)
// so the 1.64 GB stream doesn't push the 10 MB node state out of L2.
// ---------------------------------------------------------------------------
__global__ __launch_bounds__(256)
void msg_scatter(const float* __restrict__ A2, const float* __restrict__ We,
                 const int* __restrict__ src, const int* __restrict__ dst,
                 float* __restrict__ agg, int E)
{
    const int w = threadIdx.x >> 5;
    const int l = threadIdx.x & 31;
    const int e = blockIdx.x * 8 + w;
    __shared__ float hs[8][64];
    if (e >= E) return;                       // warp-uniform exit

    const int s = src[e], d = dst[e];
    hs[w][l]      = A2[s * 128 + 64 + l];
    hs[w][l + 32] = A2[s * 128 + 96 + l];
    __syncwarp();

    const float2* w2 = reinterpret_cast<const float2*>(We + (size_t)e * 4096) + l;
    float2 p0 = make_float2(0.f, 0.f), p1 = make_float2(0.f, 0.f);
#pragma unroll
    for (int i = 0; i < 64; i += 2) {
        float2 wa = __ldcs(w2 + (size_t)i * 32);
        float2 wb = __ldcs(w2 + (size_t)(i + 1) * 32);
        float h0 = hs[w][i], h1 = hs[w][i + 1];
        p0.x += h0 * wa.x; p0.y += h0 * wa.y;
        p1.x += h1 * wb.x; p1.y += h1 * wb.y;
    }
    atomicAdd(&agg[d * 64 + 2 * l],     p0.x + p1.x);
    atomicAdd(&agg[d * 64 + 2 * l + 1], p0.y + p1.y);
}

// x-part of A2: A2[v,0:64] = relu(agg[v] + b_conv)
__global__ void xrelu_kernel(const float* __restrict__ agg,
                             const float* __restrict__ b_conv,
                             float* __restrict__ A2, int total)
{
    int i = blockIdx.x * blockDim.x + threadIdx.x;
    if (i < total) {
        int v = i >> 6, j = i & 63;
        A2[v * 128 + j] = fmaxf(agg[i] + b_conv[j], 0.f);
    }
}

// GRU gates from fused pre-activations G = [r_sum, z_sum, i_n, h_n];
// updates h in-place (A2[:,64:128]) and re-zeroes agg for the next scatter.
__global__ void gru_gates(const float* __restrict__ G, float* __restrict__ A2,
                          float* __restrict__ agg, int total)
{
    int i = blockIdx.x * blockDim.x + threadIdx.x;
    if (i < total) {
        int v = i >> 6, j = i & 63;
        const float* g = G + (size_t)v * 256;
        float r = 1.f / (1.f + expf(-g[j]));
        float z = 1.f / (1.f + expf(-g[64 + j]));
        float n = tanhf(g[128 + j] + r * g[192 + j]);
        float hold = A2[v * 128 + 64 + j];
        A2[v * 128 + 64 + j] = (1.f - z) * n + z * hold;
        agg[i] = 0.f;
    }
}

// Build fused GRU weight W' (256,128) and bias b' (256) once:
// rows [0:128)  : [Wih_rz | Whh_rz]  -> r_sum, z_sum (biases summed)
// rows [128:192): [Wih_n  | 0     ]  -> i_n (b_ih)
// rows [192:256): [0      | Whh_n ]  -> h_n (b_hh)
__global__ void build_gru_w(const float* __restrict__ w_ih, const float* __restrict__ w_hh,
                            const float* __restrict__ b_ih, const float* __restrict__ b_hh,
                            float* __restrict__ Wg, float* __restrict__ bg)
{
    int idx = blockIdx.x * blockDim.x + threadIdx.x;
    if (idx < 256 * 128) {
        int r = idx >> 7, c = idx & 127;
        float v = 0.f;
        if (r < 128)      v = (c < 64) ? w_ih[r * 64 + c] : w_hh[r * 64 + (c - 64)];
        else if (r < 192) { if (c < 64)  v = w_ih[r * 64 + c]; }
        else              { if (c >= 64) v = w_hh[(r - 64) * 64 + (c - 64)]; }
        Wg[idx] = v;
    }
    if (idx < 256) {
        int r = idx;
        bg[r] = (r < 128) ? (b_ih[r] + b_hh[r]) : ((r < 192) ? b_ih[r] : b_hh[r - 64]);
    }
}

// ---------------------------------------------------------------------------
template <bool RELU>
static void gemm_big(const float* A, int lda, const float* B, const float* bias,
                     float* C, int ldc, int M, int N, int K)
{
    dim3 grid((N + 127) / 128, (M + 127) / 128);
    sgemm_db<128, 128, 16, 8, 8, RELU><<<grid, 256>>>(A, lda, B, bias, C, ldc, M, N, K);
}

template <bool RELU>
static void gemm_sm(const float* A, int lda, const float* B, const float* bias,
                    float* C, int ldc, int M, int N, int K)
{
    dim3 grid((N + 63) / 64, (M + 63) / 64);
    sgemm_db<64, 64, 16, 4, 4, RELU><<<grid, 256>>>(A, lda, B, bias, C, ldc, M, N, K);
}

extern "C" void kernel_launch(void* const* d_in, const int* in_sizes, int n_in,
                              void* d_out, int out_size)
{
    const float* node_feats = (const float*)d_in[0];
    const float* edge_feats = (const float*)d_in[1];
    const int*   src        = (const int*)  d_in[2];
    const int*   dst        = (const int*)  d_in[3];
    const float* w_p1 = (const float*)d_in[4];
    const float* b_p1 = (const float*)d_in[5];
    const float* w_p2 = (const float*)d_in[6];
    const float* b_p2 = (const float*)d_in[7];
    const float* w_e1 = (const float*)d_in[8];
    const float* b_e1 = (const float*)d_in[9];
    const float* w_e2 = (const float*)d_in[10];
    const float* b_e2 = (const float*)d_in[11];
    const float* b_conv = (const float*)d_in[12];
    const float* w_ih = (const float*)d_in[13];
    const float* w_hh = (const float*)d_in[14];
    const float* b_ih = (const float*)d_in[15];
    const float* b_hh = (const float*)d_in[16];
    const float* w_d1 = (const float*)d_in[17];
    const float* b_d1 = (const float*)d_in[18];
    const float* w_d2 = (const float*)d_in[19];
    const float* b_d2 = (const float*)d_in[20];

    const int V = in_sizes[0] / 128;   // 20000
    const int E = in_sizes[2];         // 100000

    float *We, *R, *A2, *G, *t, *agg, *d1, *Wg, *bg;
    cudaGetSymbolAddress((void**)&We,  g_We);
    cudaGetSymbolAddress((void**)&R,   g_R);
    cudaGetSymbolAddress((void**)&A2,  g_A2);
    cudaGetSymbolAddress((void**)&G,   g_G);
    cudaGetSymbolAddress((void**)&t,   g_t);
    cudaGetSymbolAddress((void**)&agg, g_agg);
    cudaGetSymbolAddress((void**)&d1,  g_d1);
    cudaGetSymbolAddress((void**)&Wg,  g_Wg);
    cudaGetSymbolAddress((void**)&bg,  g_bg);

    const int nv = V * 64;
    const int ew = (nv + 255) / 256;

    cudaMemsetAsync(agg, 0, (size_t)nv * sizeof(float), 0);
    build_gru_w<<<128, 256>>>(w_ih, w_hh, b_ih, b_hh, Wg, bg);

    // node projection -> h into A2[:,64:128]
    gemm_sm<true >(node_feats, 128, w_p1, b_p1, t,       64, V, 64, 128);
    gemm_sm<false>(t,           64, w_p2, b_p2, A2 + 64, 128, V, 64, 64);

    // edge network: R = relu(edge @ We1^T + be1); We = R @ We2^T + be2
    gemm_big<true >(edge_feats, 128, w_e1, b_e1, R,  128,  E, 128,  128);
    gemm_big<false>(R,          128, w_e2, b_e2, We, 4096, E, 4096, 128);

    // 9 message-passing steps
    for (int step = 0; step < 9; step++) {
        msg_scatter<<<(E + 7) / 8, 256>>>(A2, We, src, dst, agg, E);
        xrelu_kernel<<<ew, 256>>>(agg, b_conv, A2, nv);
        gemm_big<false>(A2, 128, Wg, bg, G, 256, V, 256, 128);
        gru_gates<<<ew, 256>>>(G, A2, agg, nv);
    }

    // decoder
    gemm_sm<true >(A2 + 64, 128, w_d1, b_d1, d1,            64, V, 64, 64);
    gemm_sm<false>(d1,       64, w_d2, b_d2, (float*)d_out, 64, V, 64, 64);
}